// round 17
// baseline (speedup 1.0000x reference)
#include <cuda_runtime.h>
#include <cstdint>

// x: (B=8, C=512, T=16, W=28, H=28) fp32, contiguous.
// All three branches decompose onto 4x4x4 = 64 window maxes m4[tt][wi][hi]
// (window 4x7x7, stride 4x7x7); temporal multiply is identity (L=1):
//   out[0]      = max over all 64                      (n=1)
//   out[1+tt2]  = mean_{wi2,hi2} max over 2x2x2 block  (n=2)
//   out[3+tt]   = mean_{wi,hi}   m4s[tt][wi][hi]       (n=4)
// R14 + deferred window phase: pm widened to one buffer per chunk so the
// streaming loop is pure wait->sync->row->sync->prefetch; all 64 window
// reductions run once after the loop. Smem 32.5 KB -> 7 blocks/SM.

#define SLICE     12544   // 16*28*28
#define TCHUNK    3136    // 4*28*28 (one temporal window-depth)
#define NBC       4096    // 8*512
#define NEG_INF   (-3.402823466e+38f)

__device__ __forceinline__ void cp_async16(uint32_t dst_smem, const void* src) {
    asm volatile("cp.async.cg.shared.global [%0], [%1], 16;\n"
                 :: "r"(dst_smem), "l"(src));
}
__device__ __forceinline__ void cp_commit() {
    asm volatile("cp.async.commit_group;\n" ::: "memory");
}
template <int N>
__device__ __forceinline__ void cp_wait() {
    asm volatile("cp.async.wait_group %0;\n" :: "n"(N) : "memory");
}

__global__ __launch_bounds__(256, 7)
void tmp3d_fused_kernel(const float* __restrict__ x, float* __restrict__ out) {
    __shared__ float tile[2 * TCHUNK];   // 2 buffers: 25.1 KB
    __shared__ float pm[4][4][112];      // per-chunk partials [tc][hi][t'*28+w], 7 KB
    __shared__ float m4s[64];            // [tt*16 + wi*4 + hi]

    const int bc  = blockIdx.x;
    const int tid = threadIdx.x;
    const float* slice = x + bc * SLICE;

    const uint32_t tile_s = (uint32_t)__cvta_generic_to_shared(&tile[0]);

    // ---- prefetch: chunk c -> buffer b (784 x 16B LDGSTS) ----
    auto prefetch = [&](int c, int b) {
        const float* src = slice + c * TCHUNK;
        const uint32_t dst = tile_s + b * (TCHUNK * 4);
        cp_async16(dst + tid * 16, src + tid * 4);
        cp_async16(dst + (tid + 256) * 16, src + (tid + 256) * 4);
        cp_async16(dst + (tid + 512) * 16, src + (tid + 512) * 4);
        if (tid < 784 - 768)
            cp_async16(dst + (tid + 768) * 16, src + (tid + 768) * 4);
        cp_commit();
    };

    prefetch(0, 0);
    prefetch(1, 1);

    #pragma unroll
    for (int tc = 0; tc < 4; tc++) {
        // entering chunk tc, groups 0..tc+1 committed; wait_group 1 => tc landed
        if (tc == 3) cp_wait<0>(); else cp_wait<1>();
        __syncthreads();

        const float* buf = tile + (tc & 1) * TCHUNK;

        // ---- row phase: 224 threads, one half-row (14 floats) each ----
        // half 0 -> hi{0,1}, half 1 -> hi{2,3}. Conflict-free LDS.128.
        if (tid < 224) {
            const int half = tid / 112;          // 0 or 1
            const int r    = tid - half * 112;   // row index (t'*28 + w)
            const float4* rp =
                reinterpret_cast<const float4*>(buf + r * 28 + half * 12);
            float4 v0 = rp[0], v1 = rp[1], v2 = rp[2], v3 = rp[3];
            float ma, mb;
            if (half == 0) {
                ma = fmaxf(fmaxf(fmaxf(v0.x, v0.y), fmaxf(v0.z, v0.w)),
                           fmaxf(fmaxf(v1.x, v1.y), v1.z));
                mb = fmaxf(fmaxf(fmaxf(v1.w, v2.x), fmaxf(v2.y, v2.z)),
                           fmaxf(fmaxf(v2.w, v3.x), v3.y));
            } else {
                ma = fmaxf(fmaxf(fmaxf(v0.z, v0.w), fmaxf(v1.x, v1.y)),
                           fmaxf(fmaxf(v1.z, v1.w), v2.x));
                mb = fmaxf(fmaxf(fmaxf(v2.y, v2.z), fmaxf(v2.w, v3.x)),
                           fmaxf(fmaxf(v3.y, v3.z), v3.w));
            }
            pm[tc][2 * half + 0][r] = ma;
            pm[tc][2 * half + 1][r] = mb;
        }
        __syncthreads();   // all buffer reads done -> safe to overwrite

        // ---- keep the DMA stream rolling: prefetch chunk tc+2 ----
        if (tc < 2) prefetch(tc + 2, tc & 1);
    }
    // pm fully written (last row phase is behind the final __syncthreads).

    // ---- deferred window phase: 64 windows, one thread each ----
    if (tid < 64) {
        const int wtc = tid >> 4;       // chunk 0..3
        const int wi  = (tid >> 2) & 3;
        const int hi  = tid & 3;
        const float* p = &pm[wtc][hi][wi * 7];
        float m = NEG_INF;
        #pragma unroll
        for (int t = 0; t < 4; t++) {
            #pragma unroll
            for (int dw = 0; dw < 7; dw++)
                m = fmaxf(m, p[t * 28 + dw]);
        }
        m4s[tid] = m;   // tid == wtc*16 + wi*4 + hi
    }
    __syncthreads();   // m4s complete

    // ---- finishing tree: 7 outputs ----
    if (tid < 7) {
        float r;
        if (tid == 0) {
            float m = m4s[0];
            #pragma unroll
            for (int i = 1; i < 64; i++) m = fmaxf(m, m4s[i]);
            r = m;
        } else if (tid < 3) {
            const int tt2 = tid - 1;
            float acc = 0.0f;
            #pragma unroll
            for (int wi2 = 0; wi2 < 2; wi2++) {
                #pragma unroll
                for (int hi2 = 0; hi2 < 2; hi2++) {
                    float m = NEG_INF;
                    #pragma unroll
                    for (int dt = 0; dt < 2; dt++)
                        #pragma unroll
                        for (int dw = 0; dw < 2; dw++)
                            #pragma unroll
                            for (int dh = 0; dh < 2; dh++)
                                m = fmaxf(m, m4s[(2*tt2 + dt) * 16 +
                                                 (2*wi2 + dw) * 4 + (2*hi2 + dh)]);
                    acc += m;
                }
            }
            r = acc * 0.25f;
        } else {
            const int tt = tid - 3;
            float acc = 0.0f;
            #pragma unroll
            for (int i = 0; i < 16; i++) acc += m4s[tt * 16 + i];
            r = acc * (1.0f / 16.0f);
        }
        out[bc * 7 + tid] = r;
    }
}

extern "C" void kernel_launch(void* const* d_in, const int* in_sizes, int n_in,
                              void* d_out, int out_size) {
    const float* x = (const float*)d_in[0];
    float* out = (float*)d_out;
    tmp3d_fused_kernel<<<NBC, 256>>>(x, out);
}